// round 12
// baseline (speedup 1.0000x reference)
#include <cuda_runtime.h>
#include <cuda_bf16.h>
#include <cstdint>

#define BN 256
#define DN 768
#define TN 128
#define NCH 24                /* 32-row chunks                      */
#define NSUB 48               /* 16-row f32 subs                    */
#define NT 384                /* threads per CTA (12 warps)         */
#define TWO_C 2.0e-5f
#define NIT 4                 /* fixed-point iterations             */

__device__ __forceinline__ uint32_t smem_u32(const void* p) {
    uint32_t a;
    asm("{ .reg .u64 t; cvta.to.shared.u64 t, %1; cvt.u32.u64 %0, t; }" : "=r"(a) : "l"(p));
    return a;
}
__device__ __forceinline__ void cp16(uint32_t dst, const void* src) {
    asm volatile("cp.async.cg.shared.global [%0], [%1], 16;" :: "r"(dst), "l"(src));
}
#define CP_COMMIT() asm volatile("cp.async.commit_group;" ::: "memory")
#define CP_WAIT3()  asm volatile("cp.async.wait_group 3;" ::: "memory")
#define CP_WAIT0()  asm volatile("cp.async.wait_group 0;" ::: "memory")
__device__ __forceinline__ void ldsm4t(uint32_t addr, uint32_t r[4]) {
    asm volatile("ldmatrix.sync.aligned.m8n8.x4.trans.shared.b16 {%0,%1,%2,%3}, [%4];"
                 : "=r"(r[0]), "=r"(r[1]), "=r"(r[2]), "=r"(r[3]) : "r"(addr));
}
__device__ __forceinline__ void mma16816(float c[4], const uint32_t a[4],
                                         uint32_t b0, uint32_t b1) {
    asm volatile("mma.sync.aligned.m16n8k16.row.col.f32.bf16.bf16.f32 "
                 "{%0,%1,%2,%3}, {%4,%5,%6,%7}, {%8,%9}, {%0,%1,%2,%3};"
                 : "+f"(c[0]), "+f"(c[1]), "+f"(c[2]), "+f"(c[3])
                 : "r"(a[0]), "r"(a[1]), "r"(a[2]), "r"(a[3]), "r"(b0), "r"(b1));
}

// ---------------------------------------------------------------------------
// One CTA per batch b, 384 threads (12 warps), 2 CTAs/SM -> 24 warps/SM.
// X_b : [D=768][T=128] f32. Woodbury:
//   w = 2C * X * (I + 2C X^T X)^{-1} y,  y = 1..128.
//
// R11 change: occupancy. The R8-R10 plateau (issue ~30%, all pipes <51%) is
// latency exposure with only 16 warps/SM. Now the 10 lower-triangle 32x32
// Gram blocks map to 10 warps (ONE block each, 32 acc regs), and the
// convert/issue/epilogue work spreads over 12 warps.
//
// SMEM pool (48 KB): [0,32K) 4-slot f32 ring (16-row subs, 8 KB) -- aliased
// to tmp[10][128]+s_sh after gram; [32K,48K) 2 bf16 stg tiles, 32x256 B,
// XOR-16B swizzle (conflict-free store AND ldmatrix).
// cp.async: per-sub cadence, wait_group 3 on 4-deep ring.
// Solve: p = M s rebuilt from triangle (forward + transposed per block).
// Epilogue: w = 2C X s, reverse order (tail chunks L2-resident), 12 warps.
// ---------------------------------------------------------------------------
__global__ __launch_bounds__(NT, 2) void rankpool_fused(const float* __restrict__ X,
                                                        float* __restrict__ W) {
    __shared__ __align__(1024) char pool[49152];
    float4* ring = reinterpret_cast<float4*>(pool);           // [4][512]
    char* stgp = pool + 32768;                                 // 2 x 8192 B

    const int b = blockIdx.x;
    const int tid = threadIdx.x;
    const int wid = tid >> 5;
    const int lane = tid & 31;
    const int g = lane >> 2, tig = lane & 3;
    const int li = lane & 7, lb3 = (lane >> 3) & 1, lb4 = lane >> 4;

    // 10 lower-triangle blocks -> warps 0..9 (warps 10,11: no MMA work)
    static const char BI[10] = {0, 1, 1, 2, 2, 2, 3, 3, 3, 3};
    static const char BJ[10] = {0, 0, 1, 0, 1, 2, 0, 1, 2, 3};
    const bool hasblk = wid < 10;
    const int bi = hasblk ? BI[wid] : 0;
    const int bj = hasblk ? BJ[wid] : 0;
    const bool offd = hasblk && (bi != bj);

    const float4* __restrict__ Xb4 =
        reinterpret_cast<const float4*>(X + (size_t)b * DN * TN);

    float acc[2][4][4];
#pragma unroll
    for (int mt = 0; mt < 2; ++mt)
#pragma unroll
        for (int nt = 0; nt < 4; ++nt)
#pragma unroll
            for (int c = 0; c < 4; ++c) acc[mt][nt][c] = 0.f;

    const uint32_t stg_addr = smem_u32(stgp);
    const uint32_t ring_addr = smem_u32(pool);
    const uint32_t arow = (uint32_t)((lb4 * 8 + li) * 256);
    const uint32_t brow = (uint32_t)((lb3 * 8 + li) * 256);
    const uint32_t li16 = (uint32_t)(li * 16);
    const uint32_t a_c16 = (uint32_t)(lb3 * 16);
    const uint32_t b_c16 = (uint32_t)(lb4 * 16);

    // convert one 16B f32 quad (f4 index f within a 16-row sub) -> bf16 stg
    auto convert_f = [&](int slot, char* base, int rbase, int f) {
        const float4 v = ring[slot * 512 + f];
        const int row = rbase + (f >> 5);
        const int seg = (f & 31) >> 1;
        const int low = (f & 1) * 8;
        __nv_bfloat162 p0 = __floats2bfloat162_rn(v.x, v.y);
        __nv_bfloat162 p1 = __floats2bfloat162_rn(v.z, v.w);
        uint2 u; u.x = *reinterpret_cast<const uint32_t*>(&p0);
        u.y = *reinterpret_cast<const uint32_t*>(&p1);
        *reinterpret_cast<uint2*>(base + row * 256 +
            ((seg * 16) ^ ((row & 7) * 16)) + low) = u;
    };
    auto convert_sub = [&](int slot, int buf, int rbase) {
        char* base = stgp + buf * 8192;
        convert_f(slot, base, rbase, tid);
        if (tid < 512 - NT) convert_f(slot, base, rbase, tid + NT);
    };
    auto issue_sub = [&](int s) {
        const uint32_t dst0 = ring_addr + (uint32_t)((s & 3) * 512 + tid) * 16u;
        cp16(dst0, Xb4 + s * 512 + tid);
        if (tid < 512 - NT)
            cp16(dst0 + (uint32_t)(NT * 16), Xb4 + s * 512 + tid + NT);
    };
    auto mma_block = [&](uint32_t kbase) {
        uint32_t aF0[4], aF1[4], bF0[4], bF1[4];
        const uint32_t ca = (uint32_t)(bi * 64);
        const uint32_t cb = (uint32_t)(bj * 64);
        ldsm4t(kbase + arow + (((ca + 0) + a_c16) ^ li16), aF0);
        ldsm4t(kbase + arow + (((ca + 32) + a_c16) ^ li16), aF1);
        ldsm4t(kbase + brow + (((cb + 0) + b_c16) ^ li16), bF0);
        ldsm4t(kbase + brow + (((cb + 32) + b_c16) ^ li16), bF1);
        mma16816(acc[0][0], aF0, bF0[0], bF0[1]);
        mma16816(acc[0][1], aF0, bF0[2], bF0[3]);
        mma16816(acc[0][2], aF0, bF1[0], bF1[1]);
        mma16816(acc[0][3], aF0, bF1[2], bF1[3]);
        mma16816(acc[1][0], aF1, bF0[0], bF0[1]);
        mma16816(acc[1][1], aF1, bF0[2], bF0[3]);
        mma16816(acc[1][2], aF1, bF1[0], bF1[1]);
        mma16816(acc[1][3], aF1, bF1[2], bF1[3]);
    };

    // ---------------- Phase 1: Gram ----------------
#pragma unroll
    for (int s = 0; s < 4; ++s) { issue_sub(s); CP_COMMIT(); }
    CP_WAIT3(); convert_sub(0, 0, 0);  issue_sub(4); CP_COMMIT();
    CP_WAIT3(); convert_sub(1, 0, 16); issue_sub(5); CP_COMMIT();

    for (int c = 0; c < NCH; ++c) {
        const uint32_t mybuf = stg_addr + (uint32_t)((c & 1) * 8192);
        __syncthreads();   // stg[c&1] fully written; stg[(c+1)&1] free

        if (hasblk) {
            mma_block(mybuf);
            mma_block(mybuf + 4096);
        }

        if (c + 1 < NCH) {
            CP_WAIT3();
            convert_sub((2 * c + 2) & 3, (c + 1) & 1, 0);
            if (2 * c + 6 < NSUB) issue_sub(2 * c + 6);
            CP_COMMIT();
            CP_WAIT3();
            convert_sub((2 * c + 3) & 3, (c + 1) & 1, 16);
            if (2 * c + 7 < NSUB) issue_sub(2 * c + 7);
            CP_COMMIT();
        }
    }
    CP_WAIT0();
    __syncthreads();                     // ring dead -> alias tmp/s_sh

    // ---------------- Phase 2: fixed-point solve ----------------
    float (*tmp)[TN] = reinterpret_cast<float (*)[TN]>(pool);   // 10 x 512 B
    float* s_sh = reinterpret_cast<float*>(pool + 10 * TN * 4);
    if (tid < 320)                       // zero tmp[10][128]
        reinterpret_cast<float4*>(&tmp[0][0])[tid] = make_float4(0.f, 0.f, 0.f, 0.f);
    if (tid < TN) s_sh[tid] = (float)(tid + 1);
    __syncthreads();

    for (int it = 0; it < NIT; ++it) {
        float pf[2][2] = {{0.f, 0.f}, {0.f, 0.f}};
        float pt[4][2] = {{0.f,0.f},{0.f,0.f},{0.f,0.f},{0.f,0.f}};
        if (hasblk) {
#pragma unroll
            for (int nt = 0; nt < 4; ++nt) {
                const float2 sv =
                    *reinterpret_cast<const float2*>(&s_sh[bj * 32 + nt * 8 + 2 * tig]);
#pragma unroll
                for (int mt = 0; mt < 2; ++mt) {
                    pf[mt][0] = fmaf(acc[mt][nt][0], sv.x, fmaf(acc[mt][nt][1], sv.y, pf[mt][0]));
                    pf[mt][1] = fmaf(acc[mt][nt][2], sv.x, fmaf(acc[mt][nt][3], sv.y, pf[mt][1]));
                }
            }
#pragma unroll
            for (int mt = 0; mt < 2; ++mt)
#pragma unroll
                for (int h = 0; h < 2; ++h) {
                    pf[mt][h] += __shfl_xor_sync(0xffffffffu, pf[mt][h], 1);
                    pf[mt][h] += __shfl_xor_sync(0xffffffffu, pf[mt][h], 2);
                }
            if (offd) {
#pragma unroll
                for (int mt = 0; mt < 2; ++mt)
#pragma unroll
                    for (int h = 0; h < 2; ++h) {
                        const float sm = s_sh[bi * 32 + mt * 16 + h * 8 + g];
#pragma unroll
                        for (int nt = 0; nt < 4; ++nt) {
                            pt[nt][0] = fmaf(acc[mt][nt][2 * h + 0], sm, pt[nt][0]);
                            pt[nt][1] = fmaf(acc[mt][nt][2 * h + 1], sm, pt[nt][1]);
                        }
                    }
#pragma unroll
                for (int nt = 0; nt < 4; ++nt)
#pragma unroll
                    for (int q = 0; q < 2; ++q) {
                        pt[nt][q] += __shfl_xor_sync(0xffffffffu, pt[nt][q], 4);
                        pt[nt][q] += __shfl_xor_sync(0xffffffffu, pt[nt][q], 8);
                        pt[nt][q] += __shfl_xor_sync(0xffffffffu, pt[nt][q], 16);
                    }
            }
            if (tig == 0) {
#pragma unroll
                for (int mt = 0; mt < 2; ++mt)
#pragma unroll
                    for (int h = 0; h < 2; ++h)
                        tmp[wid][bi * 32 + mt * 16 + h * 8 + g] = pf[mt][h];
            }
            if (offd && lane < 4) {
#pragma unroll
                for (int nt = 0; nt < 4; ++nt) {
                    tmp[wid][bj * 32 + nt * 8 + 2 * tig + 0] = pt[nt][0];
                    tmp[wid][bj * 32 + nt * 8 + 2 * tig + 1] = pt[nt][1];
                }
            }
        }
        __syncthreads();
        if (tid < TN) {
            float a = 0.f;
#pragma unroll
            for (int w = 0; w < 10; ++w) a += tmp[w][tid];
            s_sh[tid] = (float)(tid + 1) - TWO_C * a;
        }
        __syncthreads();
    }

    // ---------------- Phase 3: epilogue w = 2C * X s (reverse order) -----
    const int li8 = lane & 7, rsub = lane >> 3;
    float4 sr[4];
    {
        const float4* s4 = reinterpret_cast<const float4*>(s_sh);
#pragma unroll
        for (int i = 0; i < 4; ++i) sr[i] = s4[i * 8 + li8];
    }
    float* Wb = W + (size_t)b * DN;
#pragma unroll 2
    for (int r = DN / 48 - 1; r >= 0; --r) {     // 16 iters x 48 rows
        const int d = r * 48 + wid * 4 + rsub;
        const float4* row = Xb4 + (size_t)d * 32;
        float p0 = 0.f, p1 = 0.f;
#pragma unroll
        for (int i = 0; i < 4; i += 2) {
            const float4 v0 = row[i * 8 + li8];
            const float4 v1 = row[(i + 1) * 8 + li8];
            p0 = fmaf(v0.x, sr[i].x, fmaf(v0.y, sr[i].y,
                 fmaf(v0.z, sr[i].z, fmaf(v0.w, sr[i].w, p0))));
            p1 = fmaf(v1.x, sr[i + 1].x, fmaf(v1.y, sr[i + 1].y,
                 fmaf(v1.z, sr[i + 1].z, fmaf(v1.w, sr[i + 1].w, p1))));
        }
        float a = p0 + p1;
        a += __shfl_xor_sync(0xffffffffu, a, 1);
        a += __shfl_xor_sync(0xffffffffu, a, 2);
        a += __shfl_xor_sync(0xffffffffu, a, 4);
        if (li8 == 0) Wb[d] = TWO_C * a;
    }
}

// ---------------------------------------------------------------------------
extern "C" void kernel_launch(void* const* d_in, const int* in_sizes, int n_in,
                              void* d_out, int out_size) {
    (void)in_sizes; (void)n_in; (void)out_size;
    rankpool_fused<<<BN, NT>>>((const float*)d_in[0], (float*)d_out);
}